// round 10
// baseline (speedup 1.0000x reference)
#include <cuda_runtime.h>

// Round 10: revert attention to R6-best. Projections keep 3xTF32 mma but with
// PRECOMPUTED hi/lo split arrays (elementwise kernels; DRAM is idle) -> zero
// cvt/sub in the GEMM hot loop (R8 showed alu=26% from in-loop splits).

#define EMBED 1024
#define NHEAD 16
#define HDIM  64
#define BATCH 2
#define SEQ   2048
#define MTOT  (BATCH*SEQ)

#define PBM 128
#define PBN 128
#define PBK 16
#define PADT 136

#define PADP 68
#define ATTN_FLOATS (3*64*PADP + 128)
#define ATTN_SMEM   (ATTN_FLOATS*4)

typedef unsigned long long u64;
typedef unsigned int u32;

// ---- f32x2 helpers (attention) ----
__device__ __forceinline__ u64 pk2(float a) {
    u64 r; asm("mov.b64 %0, {%1, %1};" : "=l"(r) : "f"(a)); return r;
}
__device__ __forceinline__ void fma2(u64& d, u64 a, u64 b) {
    asm("fma.rn.f32x2 %0, %1, %2, %0;" : "+l"(d) : "l"(a), "l"(b));
}
__device__ __forceinline__ void mul2(u64& d, u64 a) {
    asm("mul.rn.f32x2 %0, %0, %1;" : "+l"(d) : "l"(a));
}
__device__ __forceinline__ float2 up2(u64 v) {
    float2 r; asm("mov.b64 {%0, %1}, %2;" : "=f"(r.x), "=f"(r.y) : "l"(v)); return r;
}

// ---- tf32 helpers ----
__device__ __forceinline__ void split_tf32(float a, u32& hi, u32& lo) {
    asm("cvt.rna.tf32.f32 %0, %1;" : "=r"(hi) : "f"(a));
    float r = a - __uint_as_float(hi);
    asm("cvt.rna.tf32.f32 %0, %1;" : "=r"(lo) : "f"(r));
}
__device__ __forceinline__ void mma8(float* c, const u32* a, const u32* b) {
    asm("mma.sync.aligned.m16n8k8.row.col.f32.tf32.tf32.f32 "
        "{%0,%1,%2,%3}, {%4,%5,%6,%7}, {%8,%9}, {%0,%1,%2,%3};"
        : "+f"(c[0]), "+f"(c[1]), "+f"(c[2]), "+f"(c[3])
        : "r"(a[0]), "r"(a[1]), "r"(a[2]), "r"(a[3]), "r"(b[0]), "r"(b[1]));
}

// Scratch
__device__ float g_q[BATCH*NHEAD*SEQ*HDIM];
__device__ float g_k[BATCH*NHEAD*SEQ*HDIM];
__device__ float g_v[BATCH*NHEAD*SEQ*HDIM];
__device__ float g_h[MTOT*EMBED];
// Precomputed tf32 splits
__device__ u32 g_xhi[MTOT*EMBED],  g_xlo[MTOT*EMBED];
__device__ u32 g_hhi[MTOT*EMBED],  g_hlo[MTOT*EMBED];
__device__ u32 g_wqhi[EMBED*EMBED], g_wqlo[EMBED*EMBED];
__device__ u32 g_wkhi[EMBED*EMBED], g_wklo[EMBED*EMBED];
__device__ u32 g_wvhi[EMBED*EMBED], g_wvlo[EMBED*EMBED];
__device__ u32 g_wohi[EMBED*EMBED], g_wolo[EMBED*EMBED];

// ---------------------------------------------------------------------------
// Elementwise tf32 split (vectorized x4)
// ---------------------------------------------------------------------------
__global__ __launch_bounds__(256) void split4_kernel(
    const float* __restrict__ in, u32* __restrict__ hi, u32* __restrict__ lo,
    int n4)
{
    int i = blockIdx.x * blockDim.x + threadIdx.x;
    if (i < n4) {
        float4 v = ((const float4*)in)[i];
        uint4 h, l;
        split_tf32(v.x, h.x, l.x);
        split_tf32(v.y, h.y, l.y);
        split_tf32(v.z, h.z, l.z);
        split_tf32(v.w, h.w, l.w);
        ((uint4*)hi)[i] = h;
        ((uint4*)lo)[i] = l;
    }
}

// ---------------------------------------------------------------------------
// 128x128 tf32-mma GEMM body on precomputed splits. No cvt in loop.
// 8 warps as 2(m) x 4(n); warp tile 64x32; 3 mma per tile per k8.
// ---------------------------------------------------------------------------
#define PROJ_MMA_BODY(AHI, ALO, BHI, BLO)                                      \
    __shared__ u32 Ash[PBK][PADT];                                             \
    __shared__ u32 Asl[PBK][PADT];                                             \
    __shared__ u32 Bsh[PBK][PADT];                                             \
    __shared__ u32 Bsl[PBK][PADT];                                             \
    const int tid  = threadIdx.x;                                              \
    const int lane = tid & 31;                                                 \
    const int wid  = tid >> 5;                                                 \
    const int m0 = blockIdx.y * PBM;                                           \
    const int n0 = blockIdx.x * PBN;                                           \
    const int wm = (wid >> 2) << 6;                                            \
    const int wn = (wid & 3) << 5;                                             \
    const int g4 = lane >> 2;                                                  \
    const int t4 = lane & 3;                                                   \
    const int lr  = tid >> 1;                                                  \
    const int lc8 = (tid & 1) << 3;                                            \
    const u32* Aph = (AHI) + (size_t)(m0 + lr) * EMBED + lc8;                  \
    const u32* Apl = (ALO) + (size_t)(m0 + lr) * EMBED + lc8;                  \
    const u32* Bph = (BHI) + (size_t)(n0 + lr) * EMBED + lc8;                  \
    const u32* Bpl = (BLO) + (size_t)(n0 + lr) * EMBED + lc8;                  \
    float c[4][4][4];                                                          \
    _Pragma("unroll")                                                          \
    for (int mi = 0; mi < 4; mi++)                                             \
        _Pragma("unroll")                                                      \
        for (int ni = 0; ni < 4; ni++)                                         \
            _Pragma("unroll")                                                  \
            for (int u = 0; u < 4; u++) c[mi][ni][u] = 0.f;                    \
    uint4 ah0 = *(const uint4*)(Aph), ah1 = *(const uint4*)(Aph + 4);          \
    uint4 al0 = *(const uint4*)(Apl), al1 = *(const uint4*)(Apl + 4);          \
    uint4 bh0 = *(const uint4*)(Bph), bh1 = *(const uint4*)(Bph + 4);          \
    uint4 bl0 = *(const uint4*)(Bpl), bl1 = *(const uint4*)(Bpl + 4);          \
    for (int kb = 0; kb < EMBED; kb += PBK) {                                  \
        __syncthreads();                                                       \
        Ash[lc8+0][lr] = ah0.x; Ash[lc8+1][lr] = ah0.y;                        \
        Ash[lc8+2][lr] = ah0.z; Ash[lc8+3][lr] = ah0.w;                        \
        Ash[lc8+4][lr] = ah1.x; Ash[lc8+5][lr] = ah1.y;                        \
        Ash[lc8+6][lr] = ah1.z; Ash[lc8+7][lr] = ah1.w;                        \
        Asl[lc8+0][lr] = al0.x; Asl[lc8+1][lr] = al0.y;                        \
        Asl[lc8+2][lr] = al0.z; Asl[lc8+3][lr] = al0.w;                        \
        Asl[lc8+4][lr] = al1.x; Asl[lc8+5][lr] = al1.y;                        \
        Asl[lc8+6][lr] = al1.z; Asl[lc8+7][lr] = al1.w;                        \
        Bsh[lc8+0][lr] = bh0.x; Bsh[lc8+1][lr] = bh0.y;                        \
        Bsh[lc8+2][lr] = bh0.z; Bsh[lc8+3][lr] = bh0.w;                        \
        Bsh[lc8+4][lr] = bh1.x; Bsh[lc8+5][lr] = bh1.y;                        \
        Bsh[lc8+6][lr] = bh1.z; Bsh[lc8+7][lr] = bh1.w;                        \
        Bsl[lc8+0][lr] = bl0.x; Bsl[lc8+1][lr] = bl0.y;                        \
        Bsl[lc8+2][lr] = bl0.z; Bsl[lc8+3][lr] = bl0.w;                        \
        Bsl[lc8+4][lr] = bl1.x; Bsl[lc8+5][lr] = bl1.y;                        \
        Bsl[lc8+6][lr] = bl1.z; Bsl[lc8+7][lr] = bl1.w;                        \
        __syncthreads();                                                       \
        if (kb + PBK < EMBED) {                                                \
            ah0 = *(const uint4*)(Aph + kb + PBK);                             \
            ah1 = *(const uint4*)(Aph + kb + PBK + 4);                         \
            al0 = *(const uint4*)(Apl + kb + PBK);                             \
            al1 = *(const uint4*)(Apl + kb + PBK + 4);                         \
            bh0 = *(const uint4*)(Bph + kb + PBK);                             \
            bh1 = *(const uint4*)(Bph + kb + PBK + 4);                         \
            bl0 = *(const uint4*)(Bpl + kb + PBK);                             \
            bl1 = *(const uint4*)(Bpl + kb + PBK + 4);                         \
        }                                                                      \
        _Pragma("unroll")                                                      \
        for (int k8 = 0; k8 < PBK; k8 += 8) {                                  \
            u32 bhi[4][2], blo[4][2];                                          \
            _Pragma("unroll")                                                  \
            for (int ni = 0; ni < 4; ni++) {                                   \
                const int kc = wn + ni*8 + g4;                                 \
                bhi[ni][0] = Bsh[k8 + t4    ][kc];                             \
                bhi[ni][1] = Bsh[k8 + t4 + 4][kc];                             \
                blo[ni][0] = Bsl[k8 + t4    ][kc];                             \
                blo[ni][1] = Bsl[k8 + t4 + 4][kc];                             \
            }                                                                  \
            _Pragma("unroll")                                                  \
            for (int mi = 0; mi < 4; mi++) {                                   \
                const int r = wm + mi*16 + g4;                                 \
                u32 ahi[4], alo[4];                                            \
                ahi[0] = Ash[k8 + t4    ][r];                                  \
                ahi[1] = Ash[k8 + t4    ][r + 8];                              \
                ahi[2] = Ash[k8 + t4 + 4][r];                                  \
                ahi[3] = Ash[k8 + t4 + 4][r + 8];                              \
                alo[0] = Asl[k8 + t4    ][r];                                  \
                alo[1] = Asl[k8 + t4    ][r + 8];                              \
                alo[2] = Asl[k8 + t4 + 4][r];                                  \
                alo[3] = Asl[k8 + t4 + 4][r + 8];                              \
                _Pragma("unroll")                                              \
                for (int ni = 0; ni < 4; ni++) {                               \
                    mma8(c[mi][ni], ahi, bhi[ni]);                             \
                    mma8(c[mi][ni], ahi, blo[ni]);                             \
                    mma8(c[mi][ni], alo, bhi[ni]);                             \
                }                                                              \
            }                                                                  \
        }                                                                      \
    }

// ---------------------------------------------------------------------------
__global__ __launch_bounds__(256, 2) void qkv_proj_kernel(
    const float* __restrict__ bq,
    const float* __restrict__ bk,
    const float* __restrict__ bv)
{
    const int z = blockIdx.z;
    const u32 *Whi, *Wlo; const float* bias; float* Out;
    if (z == 0)      { Whi = g_wqhi; Wlo = g_wqlo; bias = bq; Out = g_q; }
    else if (z == 1) { Whi = g_wkhi; Wlo = g_wklo; bias = bk; Out = g_k; }
    else             { Whi = g_wvhi; Wlo = g_wvlo; bias = bv; Out = g_v; }

    PROJ_MMA_BODY(g_xhi, g_xlo, Whi, Wlo)

#pragma unroll
    for (int mi = 0; mi < 4; mi++) {
#pragma unroll
        for (int ni = 0; ni < 4; ni++) {
            const int col = n0 + wn + ni*8 + 2*t4;
            const int h   = col >> 6;
            const int d   = col & 63;
            float2 bb = *(const float2*)&bias[col];
#pragma unroll
            for (int half = 0; half < 2; half++) {
                int row = m0 + wm + mi*16 + g4 + half*8;
                int b   = row >> 11;
                int n   = row & (SEQ - 1);
                float2 o = make_float2(c[mi][ni][2*half+0] + bb.x,
                                       c[mi][ni][2*half+1] + bb.y);
                *(float2*)&Out[((size_t)(b*NHEAD + h)*SEQ + n)*HDIM + d] = o;
            }
        }
    }
}

// ---------------------------------------------------------------------------
__global__ __launch_bounds__(256, 2) void out_proj_kernel(
    const float* __restrict__ bo, float* __restrict__ Outp)
{
    PROJ_MMA_BODY(g_hhi, g_hlo, g_wohi, g_wolo)

#pragma unroll
    for (int mi = 0; mi < 4; mi++) {
#pragma unroll
        for (int ni = 0; ni < 4; ni++) {
            const int col = n0 + wn + ni*8 + 2*t4;
            float2 bb = *(const float2*)&bo[col];
#pragma unroll
            for (int half = 0; half < 2; half++) {
                int row = m0 + wm + mi*16 + g4 + half*8;
                float2 o = make_float2(c[mi][ni][2*half+0] + bb.x,
                                       c[mi][ni][2*half+1] + bb.y);
                *(float2*)&Outp[(size_t)row * EMBED + col] = o;
            }
        }
    }
}

// ---------------------------------------------------------------------------
// Flash attention (R6 measured-best): f32x2 inner loops, shared K/V buffer.
// ---------------------------------------------------------------------------
__global__ __launch_bounds__(256, 2) void attn_kernel()
{
    extern __shared__ float sm[];
    float* Qs  = sm;
    float* KVs = sm + 64*PADP;
    float* Ps  = sm + 2*64*PADP;
    float* corr_s = sm + 3*64*PADP;
    float* l_s    = corr_s + 64;

    const int tid = threadIdx.x;
    const int bh  = blockIdx.y;
    const int q0  = blockIdx.x << 6;
    const float* Qg = g_q + (size_t)bh * SEQ * HDIM;
    const float* Kg = g_k + (size_t)bh * SEQ * HDIM;
    const float* Vg = g_v + (size_t)bh * SEQ * HDIM;

    const int lr = tid >> 2;
    const int ty = tid >> 4;
    const int tx = tid & 15;
    const int g   = tid >> 6;
    const int t64 = tid & 63;
    const int tr  = t64 >> 3;
    const int tc  = t64 & 7;

#pragma unroll
    for (int it = 0; it < 4; it++) {
        int d = it * 16 + ((tid & 3) << 2);
        float4 v = *(const float4*)&Qg[(size_t)(q0 + lr) * HDIM + d];
        Qs[(d+0)*PADP + lr] = v.x;  Qs[(d+1)*PADP + lr] = v.y;
        Qs[(d+2)*PADP + lr] = v.z;  Qs[(d+3)*PADP + lr] = v.w;
    }

    float m_run[4], l_run[4];
    u64 o2[8][4];
#pragma unroll
    for (int i = 0; i < 4; i++) { m_run[i] = -1e30f; l_run[i] = 0.f; }
#pragma unroll
    for (int i = 0; i < 8; i++)
#pragma unroll
        for (int j = 0; j < 4; j++) o2[i][j] = 0ull;

    for (int k0 = 0; k0 < SEQ; k0 += 64) {
        __syncthreads();
#pragma unroll
        for (int it = 0; it < 4; it++) {
            int d = it * 16 + ((tid & 3) << 2);
            float4 kv = *(const float4*)&Kg[(size_t)(k0 + lr) * HDIM + d];
            KVs[(d+0)*PADP + lr] = kv.x;  KVs[(d+1)*PADP + lr] = kv.y;
            KVs[(d+2)*PADP + lr] = kv.z;  KVs[(d+3)*PADP + lr] = kv.w;
        }
        __syncthreads();

        u64 s2[4][2] = {{0ull,0ull},{0ull,0ull},{0ull,0ull},{0ull,0ull}};
#pragma unroll 8
        for (int d = 0; d < 64; d++) {
            float4 av = *(const float4*)&Qs[d*PADP + (ty<<2)];
            const u64* bp = (const u64*)&KVs[d*PADP + (tx<<2)];
            u64 b0 = bp[0], b1 = bp[1];
            float ar[4] = {av.x, av.y, av.z, av.w};
#pragma unroll
            for (int i = 0; i < 4; i++) {
                u64 av2 = pk2(ar[i]);
                fma2(s2[i][0], av2, b0);
                fma2(s2[i][1], av2, b1);
            }
        }

#pragma unroll
        for (int i = 0; i < 4; i++) {
            float2 q0p = up2(s2[i][0]), q1p = up2(s2[i][1]);
            float s[4] = {q0p.x*8.0f, q0p.y*8.0f, q1p.x*8.0f, q1p.y*8.0f};
            float mx = fmaxf(fmaxf(s[0], s[1]), fmaxf(s[2], s[3]));
            mx = fmaxf(mx, __shfl_xor_sync(0xffffffffu, mx, 8, 16));
            mx = fmaxf(mx, __shfl_xor_sync(0xffffffffu, mx, 4, 16));
            mx = fmaxf(mx, __shfl_xor_sync(0xffffffffu, mx, 2, 16));
            mx = fmaxf(mx, __shfl_xor_sync(0xffffffffu, mx, 1, 16));
            float mnew = fmaxf(m_run[i], mx);
            float corr = __expf(m_run[i] - mnew);
            float rs = 0.f;
#pragma unroll
            for (int j = 0; j < 4; j++) {
                float p = __expf(s[j] - mnew);
                s[j] = p; rs += p;
            }
            rs += __shfl_xor_sync(0xffffffffu, rs, 8, 16);
            rs += __shfl_xor_sync(0xffffffffu, rs, 4, 16);
            rs += __shfl_xor_sync(0xffffffffu, rs, 2, 16);
            rs += __shfl_xor_sync(0xffffffffu, rs, 1, 16);
            l_run[i] = l_run[i] * corr + rs;
            m_run[i] = mnew;
            if (tx == 0) corr_s[(ty<<2)+i] = corr;
            *(float4*)&Ps[((ty<<2)+i)*PADP + (tx<<2)] =
                make_float4(s[0], s[1], s[2], s[3]);
        }
        __syncthreads();

#pragma unroll
        for (int it = 0; it < 4; it++) {
            int d = it * 16 + ((tid & 3) << 2);
            float4 vv = *(const float4*)&Vg[(size_t)(k0 + lr) * HDIM + d];
            *(float4*)&KVs[lr * PADP + d] = vv;
        }
        __syncthreads();

#pragma unroll
        for (int rr = 0; rr < 8; rr++) {
            u64 c2 = pk2(corr_s[tr*8 + rr]);
            mul2(o2[rr][0], c2); mul2(o2[rr][1], c2);
            mul2(o2[rr][2], c2); mul2(o2[rr][3], c2);
        }

        const int kbase = g << 4;
#pragma unroll
        for (int c4 = 0; c4 < 16; c4 += 4) {
            const int kk = kbase + c4;
            u64 v2[4][4];
#pragma unroll
            for (int u = 0; u < 4; u++) {
                const u64* vp0 = (const u64*)&KVs[(kk+u)*PADP + (tc<<2)];
                const u64* vp1 = (const u64*)&KVs[(kk+u)*PADP + 32 + (tc<<2)];
                v2[u][0] = vp0[0]; v2[u][1] = vp0[1];
                v2[u][2] = vp1[0]; v2[u][3] = vp1[1];
            }
#pragma unroll
            for (int rr = 0; rr < 8; rr++) {
                float4 p = *(const float4*)&Ps[(tr*8+rr)*PADP + kk];
                float pa[4] = {p.x, p.y, p.z, p.w};
#pragma unroll
                for (int u = 0; u < 4; u++) {
                    u64 p2 = pk2(pa[u]);
                    fma2(o2[rr][0], p2, v2[u][0]);
                    fma2(o2[rr][1], p2, v2[u][1]);
                    fma2(o2[rr][2], p2, v2[u][2]);
                    fma2(o2[rr][3], p2, v2[u][3]);
                }
            }
        }
    }

    float o[8][8];
#pragma unroll
    for (int rr = 0; rr < 8; rr++) {
        float2 p0 = up2(o2[rr][0]), p1 = up2(o2[rr][1]);
        float2 p2 = up2(o2[rr][2]), p3 = up2(o2[rr][3]);
        o[rr][0]=p0.x; o[rr][1]=p0.y; o[rr][2]=p1.x; o[rr][3]=p1.y;
        o[rr][4]=p2.x; o[rr][5]=p2.y; o[rr][6]=p3.x; o[rr][7]=p3.y;
    }

    if (tx == 0) {
#pragma unroll
        for (int i = 0; i < 4; i++) l_s[(ty<<2)+i] = l_run[i];
    }
    __syncthreads();

    if (g > 0) {
        float* mb = sm + (g-1)*(64*PADP) + t64*PADP;
#pragma unroll
        for (int rr = 0; rr < 8; rr++) {
            *(float4*)&mb[rr*8 + 0] = make_float4(o[rr][0], o[rr][1], o[rr][2], o[rr][3]);
            *(float4*)&mb[rr*8 + 4] = make_float4(o[rr][4], o[rr][5], o[rr][6], o[rr][7]);
        }
    }
    __syncthreads();

    if (g == 0) {
        const int b = bh >> 4;
        const int h = bh & 15;
#pragma unroll
        for (int gg = 0; gg < 3; gg++) {
            const float* mb = sm + gg*(64*PADP) + t64*PADP;
#pragma unroll
            for (int rr = 0; rr < 8; rr++) {
                float4 p0 = *(const float4*)&mb[rr*8 + 0];
                float4 p1 = *(const float4*)&mb[rr*8 + 4];
                o[rr][0] += p0.x; o[rr][1] += p0.y; o[rr][2] += p0.z; o[rr][3] += p0.w;
                o[rr][4] += p1.x; o[rr][5] += p1.y; o[rr][6] += p1.z; o[rr][7] += p1.w;
            }
        }
#pragma unroll
        for (int rr = 0; rr < 8; rr++) {
            int row = tr*8 + rr;
            float inv = 1.0f / l_s[row];
            int q = q0 + row;
            float* dst = &g_h[((size_t)(b*SEQ + q))*EMBED + h*HDIM];
            *(float4*)&dst[(tc<<2)] =
                make_float4(o[rr][0]*inv, o[rr][1]*inv, o[rr][2]*inv, o[rr][3]*inv);
            *(float4*)&dst[32 + (tc<<2)] =
                make_float4(o[rr][4]*inv, o[rr][5]*inv, o[rr][6]*inv, o[rr][7]*inv);
        }
    }
}

// ---------------------------------------------------------------------------
extern "C" void kernel_launch(void* const* d_in, const int* in_sizes, int n_in,
                              void* d_out, int out_size)
{
    const float* x  = (const float*)d_in[0];
    const float* Wq = (const float*)d_in[1];
    const float* bq = (const float*)d_in[2];
    const float* Wk = (const float*)d_in[3];
    const float* bk = (const float*)d_in[4];
    const float* Wv = (const float*)d_in[5];
    const float* bv = (const float*)d_in[6];
    const float* Wo = (const float*)d_in[7];
    const float* bo = (const float*)d_in[8];
    float* out = (float*)d_out;

    cudaFuncSetAttribute(attn_kernel,
                         cudaFuncAttributeMaxDynamicSharedMemorySize, ATTN_SMEM);

    u32 *xhi, *xlo, *hhi, *hlo;
    u32 *wqh, *wql, *wkh, *wkl, *wvh, *wvl, *woh, *wol;
    cudaGetSymbolAddress((void**)&xhi, g_xhi);
    cudaGetSymbolAddress((void**)&xlo, g_xlo);
    cudaGetSymbolAddress((void**)&hhi, g_hhi);
    cudaGetSymbolAddress((void**)&hlo, g_hlo);
    cudaGetSymbolAddress((void**)&wqh, g_wqhi);
    cudaGetSymbolAddress((void**)&wql, g_wqlo);
    cudaGetSymbolAddress((void**)&wkh, g_wkhi);
    cudaGetSymbolAddress((void**)&wkl, g_wklo);
    cudaGetSymbolAddress((void**)&wvh, g_wvhi);
    cudaGetSymbolAddress((void**)&wvl, g_wvlo);
    cudaGetSymbolAddress((void**)&woh, g_wohi);
    cudaGetSymbolAddress((void**)&wol, g_wolo);
    float* hptr;
    cudaGetSymbolAddress((void**)&hptr, g_h);

    const int NW4 = (EMBED*EMBED)/4;      // 262144
    const int NX4 = (MTOT*EMBED)/4;       // 1048576
    split4_kernel<<<(NX4+255)/256, 256>>>(x,  xhi, xlo, NX4);
    split4_kernel<<<(NW4+255)/256, 256>>>(Wq, wqh, wql, NW4);
    split4_kernel<<<(NW4+255)/256, 256>>>(Wk, wkh, wkl, NW4);
    split4_kernel<<<(NW4+255)/256, 256>>>(Wv, wvh, wvl, NW4);
    split4_kernel<<<(NW4+255)/256, 256>>>(Wo, woh, wol, NW4);

    dim3 gproj(EMBED / PBN, MTOT / PBM, 3);
    qkv_proj_kernel<<<gproj, 256>>>(bq, bk, bv);

    dim3 gattn(SEQ / 64, BATCH * NHEAD);
    attn_kernel<<<gattn, 256, ATTN_SMEM>>>();

    split4_kernel<<<(NX4+255)/256, 256>>>(hptr, hhi, hlo, NX4);

    dim3 gout(EMBED / PBN, MTOT / PBM);
    out_proj_kernel<<<gout, 256>>>(bo, out);
}

// round 11
// speedup vs baseline: 1.1919x; 1.1919x over previous
#include <cuda_runtime.h>

// Round 11: tf32 split computed ONCE at smem-staging time (fp32 from global,
// hi/lo into smem) -> zero split ops and zero extra global traffic in the mma
// hot loop. R8 split per-fragment (alu=26%); R10 split via global (2x LDG).
// Attention = R6 measured-best, untouched.

#define EMBED 1024
#define NHEAD 16
#define HDIM  64
#define BATCH 2
#define SEQ   2048
#define MTOT  (BATCH*SEQ)

#define PBM 128
#define PBN 128
#define PBK 16
#define PADT 136

#define PADP 68
#define ATTN_FLOATS (3*64*PADP + 128)
#define ATTN_SMEM   (ATTN_FLOATS*4)

typedef unsigned long long u64;
typedef unsigned int u32;

// ---- f32x2 helpers (attention) ----
__device__ __forceinline__ u64 pk2(float a) {
    u64 r; asm("mov.b64 %0, {%1, %1};" : "=l"(r) : "f"(a)); return r;
}
__device__ __forceinline__ void fma2(u64& d, u64 a, u64 b) {
    asm("fma.rn.f32x2 %0, %1, %2, %0;" : "+l"(d) : "l"(a), "l"(b));
}
__device__ __forceinline__ void mul2(u64& d, u64 a) {
    asm("mul.rn.f32x2 %0, %0, %1;" : "+l"(d) : "l"(a));
}
__device__ __forceinline__ float2 up2(u64 v) {
    float2 r; asm("mov.b64 {%0, %1}, %2;" : "=f"(r.x), "=f"(r.y) : "l"(v)); return r;
}

// ---- tf32 helpers ----
__device__ __forceinline__ void split_tf32(float a, u32& hi, u32& lo) {
    asm("cvt.rna.tf32.f32 %0, %1;" : "=r"(hi) : "f"(a));
    float r = a - __uint_as_float(hi);
    asm("cvt.rna.tf32.f32 %0, %1;" : "=r"(lo) : "f"(r));
}
__device__ __forceinline__ void mma8(float* c, const u32* a, const u32* b) {
    asm("mma.sync.aligned.m16n8k8.row.col.f32.tf32.tf32.f32 "
        "{%0,%1,%2,%3}, {%4,%5,%6,%7}, {%8,%9}, {%0,%1,%2,%3};"
        : "+f"(c[0]), "+f"(c[1]), "+f"(c[2]), "+f"(c[3])
        : "r"(a[0]), "r"(a[1]), "r"(a[2]), "r"(a[3]), "r"(b[0]), "r"(b[1]));
}

__device__ float g_q[BATCH*NHEAD*SEQ*HDIM];
__device__ float g_k[BATCH*NHEAD*SEQ*HDIM];
__device__ float g_v[BATCH*NHEAD*SEQ*HDIM];
__device__ float g_h[MTOT*EMBED];

// ---------------------------------------------------------------------------
// 128x128 tf32-mma GEMM body. fp32 loaded from global (R8 traffic), split at
// STS time into hi/lo smem; hot loop = LDS + mma only.
// 8 warps as 2(m) x 4(n); warp tile 64x32; 3 mma per tile per k8.
// ---------------------------------------------------------------------------
#define STS_SPLIT(DH, DL, J, V)                                                \
    { u32 _h, _l; split_tf32((V), _h, _l);                                     \
      DH[lc8+(J)][lr] = _h; DL[lc8+(J)][lr] = _l; }

#define PROJ_MMA_BODY(APTR, WPTR)                                              \
    __shared__ u32 Ash[PBK][PADT];                                             \
    __shared__ u32 Asl[PBK][PADT];                                             \
    __shared__ u32 Bsh[PBK][PADT];                                             \
    __shared__ u32 Bsl[PBK][PADT];                                             \
    const int tid  = threadIdx.x;                                              \
    const int lane = tid & 31;                                                 \
    const int wid  = tid >> 5;                                                 \
    const int m0 = blockIdx.y * PBM;                                           \
    const int n0 = blockIdx.x * PBN;                                           \
    const int wm = (wid >> 2) << 6;                                            \
    const int wn = (wid & 3) << 5;                                             \
    const int g4 = lane >> 2;                                                  \
    const int t4 = lane & 3;                                                   \
    const int lr  = tid >> 1;                                                  \
    const int lc8 = (tid & 1) << 3;                                            \
    const float* Ap = (APTR) + (size_t)(m0 + lr) * EMBED + lc8;                \
    const float* Wp = (WPTR) + (size_t)(n0 + lr) * EMBED + lc8;                \
    float c[4][4][4];                                                          \
    _Pragma("unroll")                                                          \
    for (int mi = 0; mi < 4; mi++)                                             \
        _Pragma("unroll")                                                      \
        for (int ni = 0; ni < 4; ni++)                                         \
            _Pragma("unroll")                                                  \
            for (int u = 0; u < 4; u++) c[mi][ni][u] = 0.f;                    \
    float4 a0 = *(const float4*)(Ap);                                          \
    float4 a1 = *(const float4*)(Ap + 4);                                      \
    float4 w0 = *(const float4*)(Wp);                                          \
    float4 w1 = *(const float4*)(Wp + 4);                                      \
    for (int kb = 0; kb < EMBED; kb += PBK) {                                  \
        __syncthreads();                                                       \
        STS_SPLIT(Ash, Asl, 0, a0.x)  STS_SPLIT(Ash, Asl, 1, a0.y)             \
        STS_SPLIT(Ash, Asl, 2, a0.z)  STS_SPLIT(Ash, Asl, 3, a0.w)             \
        STS_SPLIT(Ash, Asl, 4, a1.x)  STS_SPLIT(Ash, Asl, 5, a1.y)             \
        STS_SPLIT(Ash, Asl, 6, a1.z)  STS_SPLIT(Ash, Asl, 7, a1.w)             \
        STS_SPLIT(Bsh, Bsl, 0, w0.x)  STS_SPLIT(Bsh, Bsl, 1, w0.y)             \
        STS_SPLIT(Bsh, Bsl, 2, w0.z)  STS_SPLIT(Bsh, Bsl, 3, w0.w)             \
        STS_SPLIT(Bsh, Bsl, 4, w1.x)  STS_SPLIT(Bsh, Bsl, 5, w1.y)             \
        STS_SPLIT(Bsh, Bsl, 6, w1.z)  STS_SPLIT(Bsh, Bsl, 7, w1.w)             \
        __syncthreads();                                                       \
        if (kb + PBK < EMBED) {                                                \
            a0 = *(const float4*)(Ap + kb + PBK);                              \
            a1 = *(const float4*)(Ap + kb + PBK + 4);                          \
            w0 = *(const float4*)(Wp + kb + PBK);                              \
            w1 = *(const float4*)(Wp + kb + PBK + 4);                          \
        }                                                                      \
        _Pragma("unroll")                                                      \
        for (int k8 = 0; k8 < PBK; k8 += 8) {                                  \
            u32 bhi[4][2], blo[4][2];                                          \
            _Pragma("unroll")                                                  \
            for (int ni = 0; ni < 4; ni++) {                                   \
                const int kc = wn + ni*8 + g4;                                 \
                bhi[ni][0] = Bsh[k8 + t4    ][kc];                             \
                bhi[ni][1] = Bsh[k8 + t4 + 4][kc];                             \
                blo[ni][0] = Bsl[k8 + t4    ][kc];                             \
                blo[ni][1] = Bsl[k8 + t4 + 4][kc];                             \
            }                                                                  \
            _Pragma("unroll")                                                  \
            for (int mi = 0; mi < 4; mi++) {                                   \
                const int r = wm + mi*16 + g4;                                 \
                u32 ahi[4], alo[4];                                            \
                ahi[0] = Ash[k8 + t4    ][r];                                  \
                ahi[1] = Ash[k8 + t4    ][r + 8];                              \
                ahi[2] = Ash[k8 + t4 + 4][r];                                  \
                ahi[3] = Ash[k8 + t4 + 4][r + 8];                              \
                alo[0] = Asl[k8 + t4    ][r];                                  \
                alo[1] = Asl[k8 + t4    ][r + 8];                              \
                alo[2] = Asl[k8 + t4 + 4][r];                                  \
                alo[3] = Asl[k8 + t4 + 4][r + 8];                              \
                _Pragma("unroll")                                              \
                for (int ni = 0; ni < 4; ni++) {                               \
                    mma8(c[mi][ni], ahi, bhi[ni]);                             \
                    mma8(c[mi][ni], ahi, blo[ni]);                             \
                    mma8(c[mi][ni], alo, bhi[ni]);                             \
                }                                                              \
            }                                                                  \
        }                                                                      \
    }

// ---------------------------------------------------------------------------
__global__ __launch_bounds__(256, 2) void qkv_proj_kernel(
    const float* __restrict__ X,
    const float* __restrict__ Wq, const float* __restrict__ bq,
    const float* __restrict__ Wk, const float* __restrict__ bk,
    const float* __restrict__ Wv, const float* __restrict__ bv)
{
    const int z = blockIdx.z;
    const float *W, *bias; float* Out;
    if (z == 0)      { W = Wq; bias = bq; Out = g_q; }
    else if (z == 1) { W = Wk; bias = bk; Out = g_k; }
    else             { W = Wv; bias = bv; Out = g_v; }

    PROJ_MMA_BODY(X, W)

#pragma unroll
    for (int mi = 0; mi < 4; mi++) {
#pragma unroll
        for (int ni = 0; ni < 4; ni++) {
            const int col = n0 + wn + ni*8 + 2*t4;
            const int h   = col >> 6;
            const int d   = col & 63;
            float2 bb = *(const float2*)&bias[col];
#pragma unroll
            for (int half = 0; half < 2; half++) {
                int row = m0 + wm + mi*16 + g4 + half*8;
                int b   = row >> 11;
                int n   = row & (SEQ - 1);
                float2 o = make_float2(c[mi][ni][2*half+0] + bb.x,
                                       c[mi][ni][2*half+1] + bb.y);
                *(float2*)&Out[((size_t)(b*NHEAD + h)*SEQ + n)*HDIM + d] = o;
            }
        }
    }
}

// ---------------------------------------------------------------------------
__global__ __launch_bounds__(256, 2) void out_proj_kernel(
    const float* __restrict__ Wo, const float* __restrict__ bo,
    float* __restrict__ Outp)
{
    PROJ_MMA_BODY(g_h, Wo)

#pragma unroll
    for (int mi = 0; mi < 4; mi++) {
#pragma unroll
        for (int ni = 0; ni < 4; ni++) {
            const int col = n0 + wn + ni*8 + 2*t4;
            float2 bb = *(const float2*)&bo[col];
#pragma unroll
            for (int half = 0; half < 2; half++) {
                int row = m0 + wm + mi*16 + g4 + half*8;
                float2 o = make_float2(c[mi][ni][2*half+0] + bb.x,
                                       c[mi][ni][2*half+1] + bb.y);
                *(float2*)&Outp[(size_t)row * EMBED + col] = o;
            }
        }
    }
}

// ---------------------------------------------------------------------------
// Flash attention (R6 measured-best): f32x2 inner loops, shared K/V buffer.
// ---------------------------------------------------------------------------
__global__ __launch_bounds__(256, 2) void attn_kernel()
{
    extern __shared__ float sm[];
    float* Qs  = sm;
    float* KVs = sm + 64*PADP;
    float* Ps  = sm + 2*64*PADP;
    float* corr_s = sm + 3*64*PADP;
    float* l_s    = corr_s + 64;

    const int tid = threadIdx.x;
    const int bh  = blockIdx.y;
    const int q0  = blockIdx.x << 6;
    const float* Qg = g_q + (size_t)bh * SEQ * HDIM;
    const float* Kg = g_k + (size_t)bh * SEQ * HDIM;
    const float* Vg = g_v + (size_t)bh * SEQ * HDIM;

    const int lr = tid >> 2;
    const int ty = tid >> 4;
    const int tx = tid & 15;
    const int g   = tid >> 6;
    const int t64 = tid & 63;
    const int tr  = t64 >> 3;
    const int tc  = t64 & 7;

#pragma unroll
    for (int it = 0; it < 4; it++) {
        int d = it * 16 + ((tid & 3) << 2);
        float4 v = *(const float4*)&Qg[(size_t)(q0 + lr) * HDIM + d];
        Qs[(d+0)*PADP + lr] = v.x;  Qs[(d+1)*PADP + lr] = v.y;
        Qs[(d+2)*PADP + lr] = v.z;  Qs[(d+3)*PADP + lr] = v.w;
    }

    float m_run[4], l_run[4];
    u64 o2[8][4];
#pragma unroll
    for (int i = 0; i < 4; i++) { m_run[i] = -1e30f; l_run[i] = 0.f; }
#pragma unroll
    for (int i = 0; i < 8; i++)
#pragma unroll
        for (int j = 0; j < 4; j++) o2[i][j] = 0ull;

    for (int k0 = 0; k0 < SEQ; k0 += 64) {
        __syncthreads();
#pragma unroll
        for (int it = 0; it < 4; it++) {
            int d = it * 16 + ((tid & 3) << 2);
            float4 kv = *(const float4*)&Kg[(size_t)(k0 + lr) * HDIM + d];
            KVs[(d+0)*PADP + lr] = kv.x;  KVs[(d+1)*PADP + lr] = kv.y;
            KVs[(d+2)*PADP + lr] = kv.z;  KVs[(d+3)*PADP + lr] = kv.w;
        }
        __syncthreads();

        u64 s2[4][2] = {{0ull,0ull},{0ull,0ull},{0ull,0ull},{0ull,0ull}};
#pragma unroll 8
        for (int d = 0; d < 64; d++) {
            float4 av = *(const float4*)&Qs[d*PADP + (ty<<2)];
            const u64* bp = (const u64*)&KVs[d*PADP + (tx<<2)];
            u64 b0 = bp[0], b1 = bp[1];
            float ar[4] = {av.x, av.y, av.z, av.w};
#pragma unroll
            for (int i = 0; i < 4; i++) {
                u64 av2 = pk2(ar[i]);
                fma2(s2[i][0], av2, b0);
                fma2(s2[i][1], av2, b1);
            }
        }

#pragma unroll
        for (int i = 0; i < 4; i++) {
            float2 q0p = up2(s2[i][0]), q1p = up2(s2[i][1]);
            float s[4] = {q0p.x*8.0f, q0p.y*8.0f, q1p.x*8.0f, q1p.y*8.0f};
            float mx = fmaxf(fmaxf(s[0], s[1]), fmaxf(s[2], s[3]));
            mx = fmaxf(mx, __shfl_xor_sync(0xffffffffu, mx, 8, 16));
            mx = fmaxf(mx, __shfl_xor_sync(0xffffffffu, mx, 4, 16));
            mx = fmaxf(mx, __shfl_xor_sync(0xffffffffu, mx, 2, 16));
            mx = fmaxf(mx, __shfl_xor_sync(0xffffffffu, mx, 1, 16));
            float mnew = fmaxf(m_run[i], mx);
            float corr = __expf(m_run[i] - mnew);
            float rs = 0.f;
#pragma unroll
            for (int j = 0; j < 4; j++) {
                float p = __expf(s[j] - mnew);
                s[j] = p; rs += p;
            }
            rs += __shfl_xor_sync(0xffffffffu, rs, 8, 16);
            rs += __shfl_xor_sync(0xffffffffu, rs, 4, 16);
            rs += __shfl_xor_sync(0xffffffffu, rs, 2, 16);
            rs += __shfl_xor_sync(0xffffffffu, rs, 1, 16);
            l_run[i] = l_run[i] * corr + rs;
            m_run[i] = mnew;
            if (tx == 0) corr_s[(ty<<2)+i] = corr;
            *(float4*)&Ps[((ty<<2)+i)*PADP + (tx<<2)] =
                make_float4(s[0], s[1], s[2], s[3]);
        }
        __syncthreads();

#pragma unroll
        for (int it = 0; it < 4; it++) {
            int d = it * 16 + ((tid & 3) << 2);
            float4 vv = *(const float4*)&Vg[(size_t)(k0 + lr) * HDIM + d];
            *(float4*)&KVs[lr * PADP + d] = vv;
        }
        __syncthreads();

#pragma unroll
        for (int rr = 0; rr < 8; rr++) {
            u64 c2 = pk2(corr_s[tr*8 + rr]);
            mul2(o2[rr][0], c2); mul2(o2[rr][1], c2);
            mul2(o2[rr][2], c2); mul2(o2[rr][3], c2);
        }

        const int kbase = g << 4;
#pragma unroll
        for (int c4 = 0; c4 < 16; c4 += 4) {
            const int kk = kbase + c4;
            u64 v2[4][4];
#pragma unroll
            for (int u = 0; u < 4; u++) {
                const u64* vp0 = (const u64*)&KVs[(kk+u)*PADP + (tc<<2)];
                const u64* vp1 = (const u64*)&KVs[(kk+u)*PADP + 32 + (tc<<2)];
                v2[u][0] = vp0[0]; v2[u][1] = vp0[1];
                v2[u][2] = vp1[0]; v2[u][3] = vp1[1];
            }
#pragma unroll
            for (int rr = 0; rr < 8; rr++) {
                float4 p = *(const float4*)&Ps[(tr*8+rr)*PADP + kk];
                float pa[4] = {p.x, p.y, p.z, p.w};
#pragma unroll
                for (int u = 0; u < 4; u++) {
                    u64 p2 = pk2(pa[u]);
                    fma2(o2[rr][0], p2, v2[u][0]);
                    fma2(o2[rr][1], p2, v2[u][1]);
                    fma2(o2[rr][2], p2, v2[u][2]);
                    fma2(o2[rr][3], p2, v2[u][3]);
                }
            }
        }
    }

    float o[8][8];
#pragma unroll
    for (int rr = 0; rr < 8; rr++) {
        float2 p0 = up2(o2[rr][0]), p1 = up2(o2[rr][1]);
        float2 p2 = up2(o2[rr][2]), p3 = up2(o2[rr][3]);
        o[rr][0]=p0.x; o[rr][1]=p0.y; o[rr][2]=p1.x; o[rr][3]=p1.y;
        o[rr][4]=p2.x; o[rr][5]=p2.y; o[rr][6]=p3.x; o[rr][7]=p3.y;
    }

    if (tx == 0) {
#pragma unroll
        for (int i = 0; i < 4; i++) l_s[(ty<<2)+i] = l_run[i];
    }
    __syncthreads();

    if (g > 0) {
        float* mb = sm + (g-1)*(64*PADP) + t64*PADP;
#pragma unroll
        for (int rr = 0; rr < 8; rr++) {
            *(float4*)&mb[rr*8 + 0] = make_float4(o[rr][0], o[rr][1], o[rr][2], o[rr][3]);
            *(float4*)&mb[rr*8 + 4] = make_float4(o[rr][4], o[rr][5], o[rr][6], o[rr][7]);
        }
    }
    __syncthreads();

    if (g == 0) {
        const int b = bh >> 4;
        const int h = bh & 15;
#pragma unroll
        for (int gg = 0; gg < 3; gg++) {
            const float* mb = sm + gg*(64*PADP) + t64*PADP;
#pragma unroll
            for (int rr = 0; rr < 8; rr++) {
                float4 p0 = *(const float4*)&mb[rr*8 + 0];
                float4 p1 = *(const float4*)&mb[rr*8 + 4];
                o[rr][0] += p0.x; o[rr][1] += p0.y; o[rr][2] += p0.z; o[rr][3] += p0.w;
                o[rr][4] += p1.x; o[rr][5] += p1.y; o[rr][6] += p1.z; o[rr][7] += p1.w;
            }
        }
#pragma unroll
        for (int rr = 0; rr < 8; rr++) {
            int row = tr*8 + rr;
            float inv = 1.0f / l_s[row];
            int q = q0 + row;
            float* dst = &g_h[((size_t)(b*SEQ + q))*EMBED + h*HDIM];
            *(float4*)&dst[(tc<<2)] =
                make_float4(o[rr][0]*inv, o[rr][1]*inv, o[rr][2]*inv, o[rr][3]*inv);
            *(float4*)&dst[32 + (tc<<2)] =
                make_float4(o[rr][4]*inv, o[rr][5]*inv, o[rr][6]*inv, o[rr][7]*inv);
        }
    }
}

// ---------------------------------------------------------------------------
extern "C" void kernel_launch(void* const* d_in, const int* in_sizes, int n_in,
                              void* d_out, int out_size)
{
    const float* x  = (const float*)d_in[0];
    const float* Wq = (const float*)d_in[1];
    const float* bq = (const float*)d_in[2];
    const float* Wk = (const float*)d_in[3];
    const float* bk = (const float*)d_in[4];
    const float* Wv = (const float*)d_in[5];
    const float* bv = (const float*)d_in[6];
    const float* Wo = (const float*)d_in[7];
    const float* bo = (const float*)d_in[8];
    float* out = (float*)d_out;

    cudaFuncSetAttribute(attn_kernel,
                         cudaFuncAttributeMaxDynamicSharedMemorySize, ATTN_SMEM);

    dim3 gproj(EMBED / PBN, MTOT / PBM, 3);
    qkv_proj_kernel<<<gproj, 256>>>(x, Wq, bq, Wk, bk, Wv, bv);

    dim3 gattn(SEQ / 64, BATCH * NHEAD);
    attn_kernel<<<gattn, 256, ATTN_SMEM>>>();

    dim3 gout(EMBED / PBN, MTOT / PBM);
    out_proj_kernel<<<gout, 256>>>(Wo, bo, out);
}